// round 4
// baseline (speedup 1.0000x reference)
#include <cuda_runtime.h>
#include <math.h>

// Problem constants (shapes fixed by the dataset)
#define NB 32
#define NA 3
#define NH 128
#define NW 128
#define NCH (NA * 6)              // 18 channels
#define NPLANE (NH * NW)          // 16384
#define NCELL (NB * NA * NPLANE)  // 1,572,864
#define EPSF 1e-7f
#define DENSE_BLOCKS 1536

// Self-cleaning scratch (zero-initialized at module load; every launch restores zeros)
__device__ int    d_clr[NCELL];    // cleared-cell dedup flags
__device__ int    d_owner[NCELL];  // winning gt index + 1 per obj cell
__device__ double d_total;         // dense noobj-BCE sum over ALL cells
__device__ double d_corr;          // correction sum (noobj terms at cleared cells)
__device__ double d_obj;           // obj BCE + bbox loss sum
__device__ int    d_nclr;          // # distinct cleared cells
__device__ int    d_nobj;          // # distinct obj cells (winners)
__device__ int    d_ticketA;       // phase-A completion counter
__device__ int    d_done;          // global block-completion ticket

__constant__ float c_aw[3] = {116.f, 156.f, 373.f};
__constant__ float c_ah[3] = { 90.f, 198.f, 326.f};

// precise variants (tail path, ~2k elements)
__device__ __forceinline__ float bce_neg(float v) {
    float s = 1.0f / (1.0f + expf(-v));
    float p = fminf(fmaxf(s, EPSF), 1.0f - EPSF);
    return -logf(1.0f - p);
}
__device__ __forceinline__ float bce_pos(float v) {
    float s = 1.0f / (1.0f + expf(-v));
    float p = fminf(fmaxf(s, EPSF), 1.0f - EPSF);
    return -logf(p);
}
// fast variant (dense path, 1.57M elements; per-term err ~1e-7, sum err << 1e-3)
__device__ __forceinline__ float bce_neg_fast(float v) {
    float s = 1.0f / (1.0f + __expf(-v));
    float p = fminf(fmaxf(s, EPSF), 1.0f - EPSF);
    return -__logf(1.0f - p);
}
__device__ __forceinline__ float sigmoidf_(float v) {
    return 1.0f / (1.0f + expf(-v));
}

// anchor IoUs + argmax for one gt box (grid units)
__device__ __forceinline__ int best_anchor(float gw, float gh,
                                           const float* awf, const float* ahf,
                                           float* ious) {
    float best = -1.0f; int bestn = 0;
#pragma unroll
    for (int a = 0; a < 3; a++) {
        float inter = fminf(gw, awf[a]) * fminf(gh, ahf[a]);
        float uni   = gw * gh + awf[a] * ahf[a] - inter;
        float iou   = inter / uni;
        ious[a] = iou;
        if (iou > best) { best = iou; bestn = a; }
    }
    return bestn;
}

__device__ __forceinline__ void block_reduce_di(double* redD, int* redI, int tid) {
    __syncthreads();
#pragma unroll
    for (int k = 128; k > 0; k >>= 1) {
        if (tid < k) { redD[tid] += redD[tid + k]; redI[tid] += redI[tid + k]; }
        __syncthreads();
    }
}

// ---------------------------------------------------------------------------
// Single fused kernel. Block roles by blockIdx.x:
//   [0, gtBlocks)                       : Phase A (dedup/clear + owner max)
//   [gtBlocks, gtBlocks+DENSE_BLOCKS)   : dense conf-BCE sum
//   [gtBlocks+DENSE_BLOCKS, +gtBlocks)  : Phase B (spin on A, obj terms, cleanup)
// Last block to increment d_done finalizes + resets scratch.
// ---------------------------------------------------------------------------
__global__ void yolo_loss_fused(const float* __restrict__ out,
                                const int*   __restrict__ gt_batch,
                                const float* __restrict__ gt_boxes,
                                const int*   __restrict__ size_h,
                                const int*   __restrict__ size_w,
                                float* __restrict__ d_out,
                                int nGts, int gtBlocks) {
    const int tid = threadIdx.x;
    const int bid = blockIdx.x;

    __shared__ double redD[256];
    __shared__ int    redI[256];

    if (bid >= gtBlocks && bid < gtBlocks + DENSE_BLOCKS) {
        // ---------------- dense conf-BCE sum ----------------
        const int idx = (bid - gtBlocks) * 256 + tid;      // 0 .. 393215
        const float4* __restrict__ o4 = (const float4*)out;
        const int plane = idx >> 12;                       // 0..95  (b*3 + a)
        const int j     = idx & 4095;
        const int b     = plane / 3;
        const int a     = plane - 3 * b;
        const size_t off = (size_t)(b * NCH + a * 6 + 4) * 4096 + j;
        float4 v = o4[off];
        float s = bce_neg_fast(v.x) + bce_neg_fast(v.y)
                + bce_neg_fast(v.z) + bce_neg_fast(v.w);

        redD[tid] = (double)s; redI[tid] = 0;
        block_reduce_di(redD, redI, tid);
        if (tid == 0) atomicAdd(&d_total, redD[0]);
    } else {
        // shared setup for gt phases
        const float stride_h = (float)((*size_h) / NH);
        const float stride_w = (float)((*size_w) / NW);
        float awf[3], ahf[3];
#pragma unroll
        for (int a = 0; a < 3; a++) { awf[a] = c_aw[a] / stride_w; ahf[a] = c_ah[a] / stride_h; }

        if (bid < gtBlocks) {
            // ---------------- Phase A ----------------
            const int g = bid * 256 + tid;
            double corr = 0.0;
            int nclr = 0;
            if (g < nGts) {
                const int b = gt_batch[g];
                float4 box = ((const float4*)gt_boxes)[g];
                float gx = box.x * (float)NW, gy = box.y * (float)NH;
                float gw = box.z * (float)NW, gh = box.w * (float)NH;
                int gi = (int)gx, gj = (int)gy;

                float ious[3];
                int bestn = best_anchor(gw, gh, awf, ahf, ious);
                const int cellbase = ((b * NA) * NH + gj) * NW + gi;
#pragma unroll
                for (int a = 0; a < 3; a++) {
                    if ((ious[a] > 0.5f) || (a == bestn)) {
                        int cell = cellbase + a * NPLANE;
                        if (atomicExch(&d_clr[cell], 1) == 0) {
                            float v = out[(size_t)(b * NCH + a * 6 + 4) * NPLANE + gj * NW + gi];
                            corr += (double)bce_neg(v);
                            nclr++;
                        }
                    }
                }
                atomicMax(&d_owner[cellbase + bestn * NPLANE], g + 1);
            }
            redD[tid] = corr; redI[tid] = nclr;
            block_reduce_di(redD, redI, tid);
            if (tid == 0) {
                if (redI[0] > 0) { atomicAdd(&d_corr, redD[0]); atomicAdd(&d_nclr, redI[0]); }
                __threadfence();                 // release phase-A writes
                atomicAdd(&d_ticketA, 1);        // signal phase B
            }
        } else {
            // ---------------- Phase B (waits on Phase A) ----------------
            if (tid == 0) {
                while (atomicAdd(&d_ticketA, 0) < gtBlocks) { __nanosleep(64); }
            }
            __syncthreads();
            __threadfence();                     // acquire phase-A writes

            const int g = (bid - gtBlocks - DENSE_BLOCKS) * 256 + tid;
            double objsum = 0.0;
            int nobj = 0;
            if (g < nGts) {
                const int b = gt_batch[g];
                float4 box = ((const float4*)gt_boxes)[g];
                float gx = box.x * (float)NW, gy = box.y * (float)NH;
                float gw = box.z * (float)NW, gh = box.w * (float)NH;
                int gi = (int)gx, gj = (int)gy;

                float ious[3];
                int bestn = best_anchor(gw, gh, awf, ahf, ious);
                const int cellbase = ((b * NA) * NH + gj) * NW + gi;
                const int cell = cellbase + bestn * NPLANE;

                if (__ldcg(&d_owner[cell]) == g + 1) {
                    const size_t base = (size_t)(b * NCH + bestn * 6) * NPLANE + gj * NW + gi;
                    float p0 = out[base];
                    float p1 = out[base + NPLANE];
                    float p2 = out[base + 2 * NPLANE];
                    float p3 = out[base + 3 * NPLANE];
                    float p4 = out[base + 4 * NPLANE];

                    float tx = gx - floorf(gx);
                    float ty = gy - floorf(gy);
                    float tw = logf(gw / awf[bestn]);
                    float th = logf(gh / ahf[bestn]);

                    float xs = sigmoidf_(p0), ys = sigmoidf_(p1);
                    float bb = (xs - tx) * (xs - tx) + (ys - ty) * (ys - ty)
                             + (p2 - tw) * (p2 - tw) + (p3 - th) * (p3 - th);
                    objsum += (double)(bb + bce_pos(p4));   // OBJ_SCALE = 1
                    nobj++;
                    d_owner[cell] = 0;   // winner cleans; losers read 0 != g+1
                }
                // cleanup dedup flags (idempotent zeroing)
#pragma unroll
                for (int a = 0; a < 3; a++) {
                    if ((ious[a] > 0.5f) || (a == bestn)) d_clr[cellbase + a * NPLANE] = 0;
                }
            }
            redD[tid] = objsum; redI[tid] = nobj;
            block_reduce_di(redD, redI, tid);
            if (tid == 0 && redI[0] > 0) {
                atomicAdd(&d_obj, redD[0]); atomicAdd(&d_nobj, redI[0]);
            }
        }
    }

    // ---------------- global completion ticket + finalize ----------------
    if (tid == 0) {
        __threadfence();
        int ticket = atomicAdd(&d_done, 1);
        if (ticket == gridDim.x - 1) {
            double total = d_total;
            double corr  = d_corr;
            double obj   = d_obj;
            int    no    = d_nobj;
            int    ncl   = d_nclr;
            double n_obj  = (double)(no > 0 ? no : 1);
            int    nno    = NCELL - ncl;
            double n_noob = (double)(nno > 0 ? nno : 1);
            d_out[0] = (float)(obj / n_obj + 100.0 * (total - corr) / n_noob);
            // reset accumulators for the next launch (self-cleaning)
            d_total = 0.0; d_corr = 0.0; d_obj = 0.0;
            d_nclr = 0; d_nobj = 0; d_ticketA = 0; d_done = 0;
        }
    }
}

extern "C" void kernel_launch(void* const* d_in, const int* in_sizes, int n_in,
                              void* d_out, int out_size) {
    const float* out      = (const float*)d_in[0];
    const int*   gt_batch = (const int*)  d_in[1];
    const float* gt_boxes = (const float*)d_in[2];
    const int*   size_h   = (const int*)  d_in[3];
    const int*   size_w   = (const int*)  d_in[4];
    float* outp = (float*)d_out;
    const int nGts = in_sizes[1];

    const int gtBlocks = (nGts + 255) / 256;
    const int grid = gtBlocks + DENSE_BLOCKS + gtBlocks;
    yolo_loss_fused<<<grid, 256>>>(out, gt_batch, gt_boxes,
                                   size_h, size_w, outp, nGts, gtBlocks);
}

// round 7
// speedup vs baseline: 1.1332x; 1.1332x over previous
#include <cuda_runtime.h>
#include <math.h>

// Problem constants (shapes fixed by the dataset)
#define NB 32
#define NA 3
#define NH 128
#define NW 128
#define NCH (NA * 6)              // 18 channels
#define NPLANE (NH * NW)          // 16384
#define NCELL (NB * NA * NPLANE)  // 1,572,864
#define EPSF 1e-7f
#define DB 128                    // dense blocks
#define DWORK 12                  // float4 per dense thread; DB*256*DWORK = 393216 exactly

// Self-cleaning scratch (zero-initialized at module load; every launch restores zeros)
__device__ int    d_clr[NCELL];    // cleared-cell dedup flags
__device__ int    d_owner[NCELL];  // winning gt index + 1 per obj cell
__device__ double d_partial[DB];   // per-dense-block partial sums (plain stores, no atomics)
__device__ double d_corr;          // correction sum (noobj terms at cleared cells)
__device__ double d_obj;           // obj BCE + bbox loss sum
__device__ int    d_nclr;          // # distinct cleared cells
__device__ int    d_nobj;          // # distinct obj cells (winners)
__device__ int    d_ticketA;       // phase-A completion counter
__device__ int    d_done;          // global block-completion ticket

__constant__ float c_aw[3] = {116.f, 156.f, 373.f};
__constant__ float c_ah[3] = { 90.f, 198.f, 326.f};

// precise variants (tail path, ~2k elements)
__device__ __forceinline__ float bce_neg(float v) {
    float s = 1.0f / (1.0f + expf(-v));
    float p = fminf(fmaxf(s, EPSF), 1.0f - EPSF);
    return -logf(1.0f - p);
}
__device__ __forceinline__ float bce_pos(float v) {
    float s = 1.0f / (1.0f + expf(-v));
    float p = fminf(fmaxf(s, EPSF), 1.0f - EPSF);
    return -logf(p);
}
// fast variant (dense path, 1.57M elements; per-term err ~1e-7, sum err << 1e-3)
__device__ __forceinline__ float bce_neg_fast(float v) {
    float s = 1.0f / (1.0f + __expf(-v));
    float p = fminf(fmaxf(s, EPSF), 1.0f - EPSF);
    return -__logf(1.0f - p);
}
__device__ __forceinline__ float sigmoidf_(float v) {
    return 1.0f / (1.0f + expf(-v));
}

// anchor IoUs + argmax for one gt box (grid units)
__device__ __forceinline__ int best_anchor(float gw, float gh,
                                           const float* awf, const float* ahf,
                                           float* ious) {
    float best = -1.0f; int bestn = 0;
#pragma unroll
    for (int a = 0; a < 3; a++) {
        float inter = fminf(gw, awf[a]) * fminf(gh, ahf[a]);
        float uni   = gw * gh + awf[a] * ahf[a] - inter;
        float iou   = inter / uni;
        ious[a] = iou;
        if (iou > best) { best = iou; bestn = a; }
    }
    return bestn;
}

__device__ __forceinline__ double warp_reduce_d(double v) {
#pragma unroll
    for (int o = 16; o > 0; o >>= 1) v += __shfl_down_sync(0xffffffffu, v, o);
    return v;
}
__device__ __forceinline__ int warp_reduce_i(int v) {
#pragma unroll
    for (int o = 16; o > 0; o >>= 1) v += __shfl_down_sync(0xffffffffu, v, o);
    return v;
}

// ---------------------------------------------------------------------------
// Single fused kernel, 144 blocks (all wave-1 resident). Roles by blockIdx.x:
//   [0, gtBlocks)            : Phase A (dedup/clear + owner max)
//   [gtBlocks, gtBlocks+DB)  : dense conf-BCE sum (12 float4/thread)
//   [gtBlocks+DB, +gtBlocks) : Phase B (spin on A, obj terms, fused cleanup)
// Epilogue: last block via ticket sums dense partials, combines, resets.
// ---------------------------------------------------------------------------
__global__ void yolo_loss_fused(const float* __restrict__ out,
                                const int*   __restrict__ gt_batch,
                                const float* __restrict__ gt_boxes,
                                const int*   __restrict__ size_h,
                                const int*   __restrict__ size_w,
                                float* __restrict__ d_out,
                                int nGts, int gtBlocks) {
    const int tid  = threadIdx.x;
    const int bid  = blockIdx.x;
    const int lane = tid & 31;
    const int wid  = tid >> 5;

    __shared__ double sredD[8];
    __shared__ int    sredI[8];
    __shared__ int    s_last;

    if (bid >= gtBlocks && bid < gtBlocks + DB) {
        // ---------------- dense conf-BCE sum ----------------
        const int t = (bid - gtBlocks) * 256 + tid;          // 0 .. 32767
        const float4* __restrict__ o4 = (const float4*)out;
        float acc = 0.0f;
#pragma unroll
        for (int k = 0; k < DWORK; k++) {
            const int idx   = t + k * (DB * 256);            // 0 .. 393215
            const int plane = idx >> 12;                     // 0..95  (b*3 + a)
            const int j     = idx & 4095;
            const int b     = plane / 3;
            const int a     = plane - 3 * b;
            float4 v = o4[(size_t)(b * NCH + a * 6 + 4) * 4096 + j];
            acc += bce_neg_fast(v.x) + bce_neg_fast(v.y)
                 + bce_neg_fast(v.z) + bce_neg_fast(v.w);
        }
        double dsum = warp_reduce_d((double)acc);
        if (lane == 0) sredD[wid] = dsum;
        __syncthreads();
        if (tid == 0) {
            double s = sredD[0];
#pragma unroll
            for (int w = 1; w < 8; w++) s += sredD[w];
            d_partial[bid - gtBlocks] = s;                   // plain store, no atomic
        }
    } else {
        // shared setup for gt phases
        const float stride_h = (float)((*size_h) / NH);
        const float stride_w = (float)((*size_w) / NW);
        float awf[3], ahf[3];
#pragma unroll
        for (int a = 0; a < 3; a++) { awf[a] = c_aw[a] / stride_w; ahf[a] = c_ah[a] / stride_h; }

        if (bid < gtBlocks) {
            // ---------------- Phase A ----------------
            const int g = bid * 256 + tid;
            double corr = 0.0;
            int nclr = 0;
            if (g < nGts) {
                const int b = gt_batch[g];
                float4 box = ((const float4*)gt_boxes)[g];
                float gx = box.x * (float)NW, gy = box.y * (float)NH;
                float gw = box.z * (float)NW, gh = box.w * (float)NH;
                int gi = (int)gx, gj = (int)gy;

                float ious[3];
                int bestn = best_anchor(gw, gh, awf, ahf, ious);
                const int cellbase = ((b * NA) * NH + gj) * NW + gi;
#pragma unroll
                for (int a = 0; a < 3; a++) {
                    if ((ious[a] > 0.5f) || (a == bestn)) {
                        int cell = cellbase + a * NPLANE;
                        if (atomicExch(&d_clr[cell], 1) == 0) {
                            float v = out[(size_t)(b * NCH + a * 6 + 4) * NPLANE + gj * NW + gi];
                            corr += (double)bce_neg(v);
                            nclr++;
                        }
                    }
                }
                atomicMax(&d_owner[cellbase + bestn * NPLANE], g + 1);
            }
            double ds = warp_reduce_d(corr);
            int    is = warp_reduce_i(nclr);
            if (lane == 0) { sredD[wid] = ds; sredI[wid] = is; }
            __syncthreads();
            if (tid == 0) {
                double s = sredD[0]; int n = sredI[0];
#pragma unroll
                for (int w = 1; w < 8; w++) { s += sredD[w]; n += sredI[w]; }
                if (n > 0) { atomicAdd(&d_corr, s); atomicAdd(&d_nclr, n); }
                __threadfence();                 // release phase-A writes
                atomicAdd(&d_ticketA, 1);        // signal phase B
            }
        } else {
            // ---------------- Phase B (waits on Phase A) ----------------
            if (tid == 0) {
                while (atomicAdd(&d_ticketA, 0) < gtBlocks) { __nanosleep(64); }
            }
            __syncthreads();
            __threadfence();                     // acquire phase-A writes

            const int g = (bid - gtBlocks - DB) * 256 + tid;
            double objsum = 0.0;
            int nobj = 0;
            if (g < nGts) {
                const int b = gt_batch[g];
                float4 box = ((const float4*)gt_boxes)[g];
                float gx = box.x * (float)NW, gy = box.y * (float)NH;
                float gw = box.z * (float)NW, gh = box.w * (float)NH;
                int gi = (int)gx, gj = (int)gy;

                float ious[3];
                int bestn = best_anchor(gw, gh, awf, ahf, ious);
                const int cellbase = ((b * NA) * NH + gj) * NW + gi;
                const int cell = cellbase + bestn * NPLANE;

                if (__ldcg(&d_owner[cell]) == g + 1) {
                    const size_t base = (size_t)(b * NCH + bestn * 6) * NPLANE + gj * NW + gi;
                    float p0 = out[base];
                    float p1 = out[base + NPLANE];
                    float p2 = out[base + 2 * NPLANE];
                    float p3 = out[base + 3 * NPLANE];
                    float p4 = out[base + 4 * NPLANE];

                    float tx = gx - floorf(gx);
                    float ty = gy - floorf(gy);
                    float tw = logf(gw / awf[bestn]);
                    float th = logf(gh / ahf[bestn]);

                    float xs = sigmoidf_(p0), ys = sigmoidf_(p1);
                    float bb = (xs - tx) * (xs - tx) + (ys - ty) * (ys - ty)
                             + (p2 - tw) * (p2 - tw) + (p3 - th) * (p3 - th);
                    objsum += (double)(bb + bce_pos(p4));   // OBJ_SCALE = 1
                    nobj++;
                    d_owner[cell] = 0;   // winner cleans; losers read 0 != g+1
                }
                // cleanup dedup flags (idempotent zeroing)
#pragma unroll
                for (int a = 0; a < 3; a++) {
                    if ((ious[a] > 0.5f) || (a == bestn)) d_clr[cellbase + a * NPLANE] = 0;
                }
            }
            double ds = warp_reduce_d(objsum);
            int    is = warp_reduce_i(nobj);
            if (lane == 0) { sredD[wid] = ds; sredI[wid] = is; }
            __syncthreads();
            if (tid == 0) {
                double s = sredD[0]; int n = sredI[0];
#pragma unroll
                for (int w = 1; w < 8; w++) { s += sredD[w]; n += sredI[w]; }
                if (n > 0) { atomicAdd(&d_obj, s); atomicAdd(&d_nobj, n); }
            }
        }
    }

    // ---------------- global completion ticket + finalize ----------------
    if (tid == 0) {
        __threadfence();
        s_last = (atomicAdd(&d_done, 1) == (int)gridDim.x - 1);
    }
    __syncthreads();
    if (s_last) {
        // parallel sum of dense partials (tid < DB each load one)
        double v = (tid < DB) ? d_partial[tid] : 0.0;
        double ds = warp_reduce_d(v);
        if (lane == 0) sredD[wid] = ds;
        __syncthreads();
        if (tid == 0) {
            double total = sredD[0];
#pragma unroll
            for (int w = 1; w < 8; w++) total += sredD[w];
            double corr  = d_corr;
            double obj   = d_obj;
            int    no    = d_nobj;
            int    ncl   = d_nclr;
            double n_obj  = (double)(no > 0 ? no : 1);
            int    nno    = NCELL - ncl;
            double n_noob = (double)(nno > 0 ? nno : 1);
            d_out[0] = (float)(obj / n_obj + 100.0 * (total - corr) / n_noob);
            // reset accumulators for the next launch (self-cleaning)
            d_corr = 0.0; d_obj = 0.0;
            d_nclr = 0; d_nobj = 0; d_ticketA = 0; d_done = 0;
        }
    }
}

extern "C" void kernel_launch(void* const* d_in, const int* in_sizes, int n_in,
                              void* d_out, int out_size) {
    const float* out      = (const float*)d_in[0];
    const int*   gt_batch = (const int*)  d_in[1];
    const float* gt_boxes = (const float*)d_in[2];
    const int*   size_h   = (const int*)  d_in[3];
    const int*   size_w   = (const int*)  d_in[4];
    float* outp = (float*)d_out;
    const int nGts = in_sizes[1];

    const int gtBlocks = (nGts + 255) / 256;    // 8 for nGts=1920
    const int grid = gtBlocks + DB + gtBlocks;  // 144 blocks, all wave-1 resident
    yolo_loss_fused<<<grid, 256>>>(out, gt_batch, gt_boxes,
                                   size_h, size_w, outp, nGts, gtBlocks);
}